// round 14
// baseline (speedup 1.0000x reference)
#include <cuda_runtime.h>
#include <stdint.h>

// 12-bit ripple-borrow subtractor on binary (0/1) float spikes.
// Boolean-exact collapse: diffs = bits of ((a-b) & 0xFFF) MSB-first,
// borrow = (a < b). Output: [B*12] diffs row-major, then [B] borrow.
//
// R13 = converged R4/R9/R12 body bit-for-bit (best: 92.3us bench, 87.4us
// ncu, 6.62 TB/s = 83.6% DRAM), single knob: TPB 256 -> 512 (grid 4096).
// Per-warp address pattern and occupancy unchanged; probes CTA-granularity
// overhead only.
//
// Session conclusions (13 rounds): ~6.6 TB/s is this chip's mixed 65/35 R/W
// stream ceiling (every flat variant with occ>=40% pins it); traffic
// (620.7 MB) is irreducible -> ~88us kernel floor, measured. Regressions:
// persistent grid, smem staging, RPT4, register-reusing store chains.
// Neutral: __stwt, predication removal.

#define TPB 512
#define ROWS_PER_THREAD 2

__device__ __forceinline__ uint32_t pack12(const uint4& w0, const uint4& w1, const uint4& w2) {
    // index 0 = MSB (bit 11) ... index 11 = LSB (bit 0); inputs are 0.0f/1.0f
    uint32_t v = 0;
    v |= (w0.x ? 1u : 0u) << 11;
    v |= (w0.y ? 1u : 0u) << 10;
    v |= (w0.z ? 1u : 0u) << 9;
    v |= (w0.w ? 1u : 0u) << 8;
    v |= (w1.x ? 1u : 0u) << 7;
    v |= (w1.y ? 1u : 0u) << 6;
    v |= (w1.z ? 1u : 0u) << 5;
    v |= (w1.w ? 1u : 0u) << 4;
    v |= (w2.x ? 1u : 0u) << 3;
    v |= (w2.y ? 1u : 0u) << 2;
    v |= (w2.z ? 1u : 0u) << 1;
    v |= (w2.w ? 1u : 0u);
    return v;
}

__device__ __forceinline__ uint32_t bitf(uint32_t d, int bit) {
    return ((d >> bit) & 1u) * 0x3F800000u;  // 1.0f bits or 0
}

__global__ void __launch_bounds__(TPB) sub12_kernel(
    const uint4* __restrict__ A4,
    const uint4* __restrict__ B4,
    uint4* __restrict__ D4,
    float* __restrict__ Borrow,
    int batch)
{
    const int tileBase = blockIdx.x * (TPB * ROWS_PER_THREAD);
    const int tid = threadIdx.x;

    int rows[ROWS_PER_THREAD];
    uint4 a[ROWS_PER_THREAD][3], b[ROWS_PER_THREAD][3];
    bool valid[ROWS_PER_THREAD];

    // Front-batched loads: all 12 LDG.128 issued before any compute.
#pragma unroll
    for (int r = 0; r < ROWS_PER_THREAD; r++) {
        const int i = tileBase + r * TPB + tid;  // block-strided warp pattern
        rows[r] = i;
        valid[r] = (i < batch);
        if (valid[r]) {
            a[r][0] = __ldcs(&A4[(size_t)i * 3 + 0]);
            a[r][1] = __ldcs(&A4[(size_t)i * 3 + 1]);
            a[r][2] = __ldcs(&A4[(size_t)i * 3 + 2]);
            b[r][0] = __ldcs(&B4[(size_t)i * 3 + 0]);
            b[r][1] = __ldcs(&B4[(size_t)i * 3 + 1]);
            b[r][2] = __ldcs(&B4[(size_t)i * 3 + 2]);
        }
    }

#pragma unroll
    for (int r = 0; r < ROWS_PER_THREAD; r++) {
        if (!valid[r]) continue;
        const int i = rows[r];

        const uint32_t ia = pack12(a[r][0], a[r][1], a[r][2]);
        const uint32_t ib = pack12(b[r][0], b[r][1], b[r][2]);
        const uint32_t d  = (ia - ib) & 0xFFFu;

        uint4 o0, o1, o2;
        o0.x = bitf(d, 11); o0.y = bitf(d, 10); o0.z = bitf(d, 9); o0.w = bitf(d, 8);
        o1.x = bitf(d, 7);  o1.y = bitf(d, 6);  o1.z = bitf(d, 5); o1.w = bitf(d, 4);
        o2.x = bitf(d, 3);  o2.y = bitf(d, 2);  o2.z = bitf(d, 1); o2.w = bitf(d, 0);

        __stcs(&D4[(size_t)i * 3 + 0], o0);
        __stcs(&D4[(size_t)i * 3 + 1], o1);
        __stcs(&D4[(size_t)i * 3 + 2], o2);
        __stcs(&Borrow[i], __uint_as_float((ia < ib) ? 0x3F800000u : 0u));
    }
}

extern "C" void kernel_launch(void* const* d_in, const int* in_sizes, int n_in,
                              void* d_out, int out_size)
{
    const uint4* A4 = (const uint4*)d_in[0];
    const uint4* B4 = (const uint4*)d_in[1];
    const int batch = in_sizes[0] / 12;

    float* out = (float*)d_out;
    uint4* D4 = (uint4*)out;
    float* Borrow = out + (size_t)batch * 12;

    const int rowsPerBlock = TPB * ROWS_PER_THREAD;
    const int blocks = (batch + rowsPerBlock - 1) / rowsPerBlock;
    sub12_kernel<<<blocks, TPB>>>(A4, B4, D4, Borrow, batch);
}

// round 15
// speedup vs baseline: 1.0093x; 1.0093x over previous
#include <cuda_runtime.h>
#include <stdint.h>

// 12-bit ripple-borrow subtractor on binary (0/1) float spikes.
// Boolean-exact collapse: diffs = bits of ((a-b) & 0xFFF) MSB-first,
// borrow = (a < b). Output: [B*12] diffs row-major, then [B] borrow.
//
// FINAL (verified best across 14 rounds: 92.3us bench / 87.4us ncu /
// 6.62 TB/s = 83.6% DRAM): flat oversubscribed launch, TPB 256, 2 rows per
// thread block-strided, __ldcs/__stcs streaming hints, all loads
// front-batched, compute into DISTINCT output registers, stores batched last.
//
// Session conclusions:
//  - ~6.6 TB/s is this chip's mixed 65/35 R/W stream ceiling; every flat
//    variant with occ >= ~40% pins it, none exceeds it.
//  - Traffic (620.7 MB) is irreducible -> ~88us kernel-time floor, measured.
//  - Regressions: persistent grid (-13%), smem staging (-12%), RPT4 / occ
//    22% (-11%), register-reusing store chains (-4%).
//  - Neutral: __stwt, predication removal, TPB 512.

#define TPB 256
#define ROWS_PER_THREAD 2

__device__ __forceinline__ uint32_t pack12(const uint4& w0, const uint4& w1, const uint4& w2) {
    // index 0 = MSB (bit 11) ... index 11 = LSB (bit 0); inputs are 0.0f/1.0f
    uint32_t v = 0;
    v |= (w0.x ? 1u : 0u) << 11;
    v |= (w0.y ? 1u : 0u) << 10;
    v |= (w0.z ? 1u : 0u) << 9;
    v |= (w0.w ? 1u : 0u) << 8;
    v |= (w1.x ? 1u : 0u) << 7;
    v |= (w1.y ? 1u : 0u) << 6;
    v |= (w1.z ? 1u : 0u) << 5;
    v |= (w1.w ? 1u : 0u) << 4;
    v |= (w2.x ? 1u : 0u) << 3;
    v |= (w2.y ? 1u : 0u) << 2;
    v |= (w2.z ? 1u : 0u) << 1;
    v |= (w2.w ? 1u : 0u);
    return v;
}

__device__ __forceinline__ uint32_t bitf(uint32_t d, int bit) {
    return ((d >> bit) & 1u) * 0x3F800000u;  // 1.0f bits or 0
}

__global__ void __launch_bounds__(TPB) sub12_kernel(
    const uint4* __restrict__ A4,
    const uint4* __restrict__ B4,
    uint4* __restrict__ D4,
    float* __restrict__ Borrow,
    int batch)
{
    const int tileBase = blockIdx.x * (TPB * ROWS_PER_THREAD);
    const int tid = threadIdx.x;

    int rows[ROWS_PER_THREAD];
    uint4 a[ROWS_PER_THREAD][3], b[ROWS_PER_THREAD][3];
    bool valid[ROWS_PER_THREAD];

    // Front-batched loads: all 12 LDG.128 issued before any compute.
#pragma unroll
    for (int r = 0; r < ROWS_PER_THREAD; r++) {
        const int i = tileBase + r * TPB + tid;  // block-strided warp pattern
        rows[r] = i;
        valid[r] = (i < batch);
        if (valid[r]) {
            a[r][0] = __ldcs(&A4[(size_t)i * 3 + 0]);
            a[r][1] = __ldcs(&A4[(size_t)i * 3 + 1]);
            a[r][2] = __ldcs(&A4[(size_t)i * 3 + 2]);
            b[r][0] = __ldcs(&B4[(size_t)i * 3 + 0]);
            b[r][1] = __ldcs(&B4[(size_t)i * 3 + 1]);
            b[r][2] = __ldcs(&B4[(size_t)i * 3 + 2]);
        }
    }

#pragma unroll
    for (int r = 0; r < ROWS_PER_THREAD; r++) {
        if (!valid[r]) continue;
        const int i = rows[r];

        const uint32_t ia = pack12(a[r][0], a[r][1], a[r][2]);
        const uint32_t ib = pack12(b[r][0], b[r][1], b[r][2]);
        const uint32_t d  = (ia - ib) & 0xFFFu;

        uint4 o0, o1, o2;
        o0.x = bitf(d, 11); o0.y = bitf(d, 10); o0.z = bitf(d, 9); o0.w = bitf(d, 8);
        o1.x = bitf(d, 7);  o1.y = bitf(d, 6);  o1.z = bitf(d, 5); o1.w = bitf(d, 4);
        o2.x = bitf(d, 3);  o2.y = bitf(d, 2);  o2.z = bitf(d, 1); o2.w = bitf(d, 0);

        __stcs(&D4[(size_t)i * 3 + 0], o0);
        __stcs(&D4[(size_t)i * 3 + 1], o1);
        __stcs(&D4[(size_t)i * 3 + 2], o2);
        __stcs(&Borrow[i], __uint_as_float((ia < ib) ? 0x3F800000u : 0u));
    }
}

extern "C" void kernel_launch(void* const* d_in, const int* in_sizes, int n_in,
                              void* d_out, int out_size)
{
    const uint4* A4 = (const uint4*)d_in[0];
    const uint4* B4 = (const uint4*)d_in[1];
    const int batch = in_sizes[0] / 12;

    float* out = (float*)d_out;
    uint4* D4 = (uint4*)out;
    float* Borrow = out + (size_t)batch * 12;

    const int rowsPerBlock = TPB * ROWS_PER_THREAD;
    const int blocks = (batch + rowsPerBlock - 1) / rowsPerBlock;
    sub12_kernel<<<blocks, TPB>>>(A4, B4, D4, Borrow, batch);
}

// round 16
// speedup vs baseline: 1.0170x; 1.0076x over previous
#include <cuda_runtime.h>
#include <stdint.h>

// 12-bit ripple-borrow subtractor on binary (0/1) float spikes.
// Boolean-exact collapse: diffs = bits of ((a-b) & 0xFFF) MSB-first,
// borrow = (a < b). Output: [B*12] diffs row-major, then [B] borrow.
//
// FINAL — converged configuration (best measured: 92.3us bench / 87.4us ncu
// / 6.62 TB/s DRAM). Flat oversubscribed launch, TPB 256, 2 rows/thread
// block-strided, __ldcs/__stcs, loads front-batched, distinct output regs,
// stores batched last.
//
// Session conclusions (15 rounds):
//  - ~6.6 TB/s is the chip's mixed 65/35 R/W stream ceiling; reached by every
//    flat variant with occ >= ~40%, exceeded by none.
//  - Traffic (620.7 MB) is irreducible -> ~88us kernel floor, measured.
//  - 48B-row-stride loads waste no DRAM sectors (warp spans are contiguous
//    across instructions); coalescing "fixes" only move L1 work (not binding).
//  - Regressions: persistent grid, smem staging, RPT4 (occ<40%), register-
//    reusing store chains. Neutral: __stwt, predication removal, TPB 512.

#define TPB 256
#define ROWS_PER_THREAD 2

__device__ __forceinline__ uint32_t pack12(const uint4& w0, const uint4& w1, const uint4& w2) {
    // index 0 = MSB (bit 11) ... index 11 = LSB (bit 0); inputs are 0.0f/1.0f
    uint32_t v = 0;
    v |= (w0.x ? 1u : 0u) << 11;
    v |= (w0.y ? 1u : 0u) << 10;
    v |= (w0.z ? 1u : 0u) << 9;
    v |= (w0.w ? 1u : 0u) << 8;
    v |= (w1.x ? 1u : 0u) << 7;
    v |= (w1.y ? 1u : 0u) << 6;
    v |= (w1.z ? 1u : 0u) << 5;
    v |= (w1.w ? 1u : 0u) << 4;
    v |= (w2.x ? 1u : 0u) << 3;
    v |= (w2.y ? 1u : 0u) << 2;
    v |= (w2.z ? 1u : 0u) << 1;
    v |= (w2.w ? 1u : 0u);
    return v;
}

__device__ __forceinline__ uint32_t bitf(uint32_t d, int bit) {
    return ((d >> bit) & 1u) * 0x3F800000u;  // 1.0f bits or 0
}

__global__ void __launch_bounds__(TPB) sub12_kernel(
    const uint4* __restrict__ A4,
    const uint4* __restrict__ B4,
    uint4* __restrict__ D4,
    float* __restrict__ Borrow,
    int batch)
{
    const int tileBase = blockIdx.x * (TPB * ROWS_PER_THREAD);
    const int tid = threadIdx.x;

    int rows[ROWS_PER_THREAD];
    uint4 a[ROWS_PER_THREAD][3], b[ROWS_PER_THREAD][3];
    bool valid[ROWS_PER_THREAD];

    // Front-batched loads: all 12 LDG.128 issued before any compute.
#pragma unroll
    for (int r = 0; r < ROWS_PER_THREAD; r++) {
        const int i = tileBase + r * TPB + tid;  // block-strided warp pattern
        rows[r] = i;
        valid[r] = (i < batch);
        if (valid[r]) {
            a[r][0] = __ldcs(&A4[(size_t)i * 3 + 0]);
            a[r][1] = __ldcs(&A4[(size_t)i * 3 + 1]);
            a[r][2] = __ldcs(&A4[(size_t)i * 3 + 2]);
            b[r][0] = __ldcs(&B4[(size_t)i * 3 + 0]);
            b[r][1] = __ldcs(&B4[(size_t)i * 3 + 1]);
            b[r][2] = __ldcs(&B4[(size_t)i * 3 + 2]);
        }
    }

#pragma unroll
    for (int r = 0; r < ROWS_PER_THREAD; r++) {
        if (!valid[r]) continue;
        const int i = rows[r];

        const uint32_t ia = pack12(a[r][0], a[r][1], a[r][2]);
        const uint32_t ib = pack12(b[r][0], b[r][1], b[r][2]);
        const uint32_t d  = (ia - ib) & 0xFFFu;

        uint4 o0, o1, o2;
        o0.x = bitf(d, 11); o0.y = bitf(d, 10); o0.z = bitf(d, 9); o0.w = bitf(d, 8);
        o1.x = bitf(d, 7);  o1.y = bitf(d, 6);  o1.z = bitf(d, 5); o1.w = bitf(d, 4);
        o2.x = bitf(d, 3);  o2.y = bitf(d, 2);  o2.z = bitf(d, 1); o2.w = bitf(d, 0);

        __stcs(&D4[(size_t)i * 3 + 0], o0);
        __stcs(&D4[(size_t)i * 3 + 1], o1);
        __stcs(&D4[(size_t)i * 3 + 2], o2);
        __stcs(&Borrow[i], __uint_as_float((ia < ib) ? 0x3F800000u : 0u));
    }
}

extern "C" void kernel_launch(void* const* d_in, const int* in_sizes, int n_in,
                              void* d_out, int out_size)
{
    const uint4* A4 = (const uint4*)d_in[0];
    const uint4* B4 = (const uint4*)d_in[1];
    const int batch = in_sizes[0] / 12;

    float* out = (float*)d_out;
    uint4* D4 = (uint4*)out;
    float* Borrow = out + (size_t)batch * 12;

    const int rowsPerBlock = TPB * ROWS_PER_THREAD;
    const int blocks = (batch + rowsPerBlock - 1) / rowsPerBlock;
    sub12_kernel<<<blocks, TPB>>>(A4, B4, D4, Borrow, batch);
}